// round 2
// baseline (speedup 1.0000x reference)
#include <cuda_runtime.h>

#define B_ 128
#define C_ 3
#define H_ 256
#define W_ 256
#define HW (H_*W_)
#define CHW (C_*HW)
#define SHIFT 32       // int(256*0.125 + 0.5)
#define CUT_HALF 25    // cut=51 -> cut//2 = 25

// Scratch: per-sample mean of raw input (allocation-free rule -> device global)
__device__ float g_mean[B_];

// Kernel 1: deterministic per-sample mean. One block per sample.
__global__ void __launch_bounds__(1024) mean_kernel(const float* __restrict__ x) {
    int b = blockIdx.x;
    const float4* xb = (const float4*)(x + (size_t)b * CHW);
    const int n4 = CHW / 4;  // 49152
    float s = 0.f;
    for (int i = threadIdx.x; i < n4; i += 1024) {
        float4 v = xb[i];
        s += (v.x + v.y) + (v.z + v.w);
    }
    // warp tree reduce (fixed order -> deterministic across runs)
    #pragma unroll
    for (int o = 16; o; o >>= 1) s += __shfl_down_sync(0xffffffffu, s, o);
    __shared__ float red[32];
    int lane = threadIdx.x & 31, wid = threadIdx.x >> 5;
    if (lane == 0) red[wid] = s;
    __syncthreads();
    if (wid == 0) {
        s = red[lane];
        #pragma unroll
        for (int o = 16; o; o >>= 1) s += __shfl_down_sync(0xffffffffu, s, o);
        if (lane == 0) g_mean[b] = s * (1.0f / (float)CHW);
    }
}

// Kernel 2: fused color + translate + cutout.
// One thread per 4 consecutive output pixels (b,h,w..w+3), all 3 channels.
// Stores are aligned float4 (fully coalesced); gather loads are scalar
// (source column offset sw is arbitrary, so no vector load possible).
__global__ void __launch_bounds__(256) aug_kernel(
    const float* __restrict__ x,
    const float* __restrict__ rb,
    const float* __restrict__ rs,
    const float* __restrict__ rc,
    const int*   __restrict__ txp,
    const int*   __restrict__ typ,
    const int*   __restrict__ oxp,
    const int*   __restrict__ oyp,
    float* __restrict__ out)
{
    int idx = blockIdx.x * blockDim.x + threadIdx.x;   // over B*H*(W/4)
    int w4 = idx & (W_/4 - 1);          // 0..63
    int h  = (idx >> 6) & (H_ - 1);
    int b  = idx >> 14;
    int w0 = w4 * 4;

    float br = __ldg(rb + b) - 0.5f;
    float sk = __ldg(rs + b) * 2.0f;
    float k  = __ldg(rc + b) + 0.5f;
    float M  = g_mean[b] + br;   // exact-math mean after brightness+saturation
    sk *= k;

    int sh = h  + __ldg(txp + b) - SHIFT;
    int ty = __ldg(typ + b) - SHIFT;
    int ox = __ldg(oxp + b);
    int oy = __ldg(oyp + b);

    bool row_valid = ((unsigned)sh < (unsigned)H_);
    bool row_cut   = (h >= ox - CUT_HALF) && (h <= ox + CUT_HALF);

    float4 o0 = {0.f,0.f,0.f,0.f}, o1 = o0, o2 = o0;
    if (row_valid) {
        const float* src = x + (size_t)b * CHW + sh * W_;
        #pragma unroll
        for (int j = 0; j < 4; j++) {
            int w  = w0 + j;
            int sw = w + ty;
            bool cut = row_cut && (w >= oy - CUT_HALF) && (w <= oy + CUT_HALF);
            if (!cut && (unsigned)sw < (unsigned)W_) {
                float x0 = __ldg(src + sw);
                float x1 = __ldg(src + sw + HW);
                float x2 = __ldg(src + sw + 2 * HW);
                float mc   = (x0 + x1 + x2) * (1.0f / 3.0f);
                float base = (mc + br - M) * k + M;
                ((float*)&o0)[j] = (x0 - mc) * sk + base;
                ((float*)&o1)[j] = (x1 - mc) * sk + base;
                ((float*)&o2)[j] = (x2 - mc) * sk + base;
            }
        }
    }
    float4* dst = (float4*)(out + (size_t)b * CHW + h * W_ + w0);
    dst[0]          = o0;
    dst[HW / 4]     = o1;
    dst[2 * HW / 4] = o2;
}

extern "C" void kernel_launch(void* const* d_in, const int* in_sizes, int n_in,
                              void* d_out, int out_size) {
    const float* x  = (const float*)d_in[0];
    const float* rb = (const float*)d_in[1];
    const float* rs = (const float*)d_in[2];
    const float* rc = (const float*)d_in[3];
    const int*   tx = (const int*)d_in[4];
    const int*   ty = (const int*)d_in[5];
    const int*   oxv = (const int*)d_in[6];
    const int*   oyv = (const int*)d_in[7];
    float* out = (float*)d_out;

    mean_kernel<<<B_, 1024>>>(x);
    aug_kernel<<<(B_ * H_ * (W_ / 4)) / 256, 256>>>(x, rb, rs, rc, tx, ty, oxv, oyv, out);
}